// round 1
// baseline (speedup 1.0000x reference)
#include <cuda_runtime.h>

#define N_EXPERTS 8
#define FDIM1 1024
#define FDIM2 512
#define NCLS 64
#define BATCH 16384

// Scratch (static device arrays: allocation-free per harness rules)
__device__ float g_H[(size_t)BATCH * FDIM2];       // 32 MB hidden activations
__device__ int   g_idx[N_EXPERTS * BATCH];         // per-expert sample row lists
__device__ int   g_cnt[N_EXPERTS];

// ---------------------------------------------------------------------------
// Kernel 0a: reset counters
__global__ void k_reset() {
    if (threadIdx.x < N_EXPERTS) g_cnt[threadIdx.x] = 0;
}

// Kernel 0b: bucket sample indices by expert
__global__ void k_bucket(const int* __restrict__ domain) {
    int i = blockIdx.x * blockDim.x + threadIdx.x;
    if (i < BATCH) {
        int e = domain[i];
        int p = atomicAdd(&g_cnt[e], 1);
        g_idx[e * BATCH + p] = i;
    }
}

// ---------------------------------------------------------------------------
// Kernel 1: H[row, :] = relu(x[row, :] @ W1[e] + b1[e]) for rows of expert e.
// Block tile: 128 (M, samples) x 64 (N, fdim2), K chunks of 32.
// 256 threads = 16x16, each thread computes an 8x4 microtile.
__global__ __launch_bounds__(256) void k_layer1(
    const float* __restrict__ x,
    const float* __restrict__ W1,
    const float* __restrict__ b1)
{
    const int e = blockIdx.z;
    const int cnt = g_cnt[e];
    const int mbase = blockIdx.x * 128;
    if (mbase >= cnt) return;
    const int nbase = blockIdx.y * 64;

    __shared__ int rows[128];
    __shared__ __align__(16) float As[32][132];  // [k][m], padded
    __shared__ __align__(16) float Bs[32][68];   // [k][n], padded

    const int t = threadIdx.x;
    if (t < 128) {
        int p = mbase + t;
        rows[t] = (p < cnt) ? g_idx[e * BATCH + p] : -1;
    }
    __syncthreads();

    const int tx = t & 15, ty = t >> 4;
    const int m0 = ty * 8, n0 = tx * 4;

    float acc[8][4];
#pragma unroll
    for (int i = 0; i < 8; i++)
#pragma unroll
        for (int j = 0; j < 4; j++) acc[i][j] = 0.0f;

    // Global-load mapping
    const int lm = t >> 1;                 // A: row 0..127
    const int lkoff = (t & 1) * 16;        // A: 16 floats (4x float4) along k
    const float* xrow = nullptr;
    {
        int r = rows[lm];
        if (r >= 0) xrow = x + (size_t)r * FDIM1;
    }
    const int bk = t >> 4;                 // B: k row (0..15, +16 for second)
    const int bn4 = (t & 15) * 4;          // B: n offset
    const float* Wbase = W1 + (size_t)e * FDIM1 * FDIM2 + nbase;

    for (int kc = 0; kc < FDIM1; kc += 32) {
        float4 av0 = {0,0,0,0}, av1 = av0, av2 = av0, av3 = av0;
        if (xrow) {
            const float4* s = reinterpret_cast<const float4*>(xrow + kc + lkoff);
            av0 = s[0]; av1 = s[1]; av2 = s[2]; av3 = s[3];
        }
        float4 bv0 = *reinterpret_cast<const float4*>(Wbase + (size_t)(kc + bk) * FDIM2 + bn4);
        float4 bv1 = *reinterpret_cast<const float4*>(Wbase + (size_t)(kc + 16 + bk) * FDIM2 + bn4);

        __syncthreads();
        // transposed A store: As[k][m]
        As[lkoff + 0][lm] = av0.x; As[lkoff + 1][lm] = av0.y;
        As[lkoff + 2][lm] = av0.z; As[lkoff + 3][lm] = av0.w;
        As[lkoff + 4][lm] = av1.x; As[lkoff + 5][lm] = av1.y;
        As[lkoff + 6][lm] = av1.z; As[lkoff + 7][lm] = av1.w;
        As[lkoff + 8][lm] = av2.x; As[lkoff + 9][lm] = av2.y;
        As[lkoff +10][lm] = av2.z; As[lkoff +11][lm] = av2.w;
        As[lkoff +12][lm] = av3.x; As[lkoff +13][lm] = av3.y;
        As[lkoff +14][lm] = av3.z; As[lkoff +15][lm] = av3.w;
        *reinterpret_cast<float4*>(&Bs[bk][bn4]) = bv0;
        *reinterpret_cast<float4*>(&Bs[16 + bk][bn4]) = bv1;
        __syncthreads();

#pragma unroll
        for (int k = 0; k < 32; k++) {
            float4 a0 = *reinterpret_cast<const float4*>(&As[k][m0]);
            float4 a1 = *reinterpret_cast<const float4*>(&As[k][m0 + 4]);
            float4 b  = *reinterpret_cast<const float4*>(&Bs[k][n0]);
            float ar[8] = {a0.x, a0.y, a0.z, a0.w, a1.x, a1.y, a1.z, a1.w};
            float br[4] = {b.x, b.y, b.z, b.w};
#pragma unroll
            for (int i = 0; i < 8; i++)
#pragma unroll
                for (int j = 0; j < 4; j++)
                    acc[i][j] = fmaf(ar[i], br[j], acc[i][j]);
        }
    }

    // epilogue: + b1, relu, scatter to H by original row
    const float* b1e = b1 + (size_t)e * FDIM2 + nbase + n0;
    float bb0 = b1e[0], bb1 = b1e[1], bb2 = b1e[2], bb3 = b1e[3];
#pragma unroll
    for (int i = 0; i < 8; i++) {
        int r = rows[m0 + i];
        if (r < 0) continue;
        float4 o;
        o.x = fmaxf(acc[i][0] + bb0, 0.0f);
        o.y = fmaxf(acc[i][1] + bb1, 0.0f);
        o.z = fmaxf(acc[i][2] + bb2, 0.0f);
        o.w = fmaxf(acc[i][3] + bb3, 0.0f);
        *reinterpret_cast<float4*>(&g_H[(size_t)r * FDIM2 + nbase + n0]) = o;
    }
}

// ---------------------------------------------------------------------------
// Kernel 2: logits = H @ W2[e] + b2[e]; softmax; scatter to out.
// Block: 16 samples of one expert, 256 threads. f staged in chunks of 64.
__global__ __launch_bounds__(256) void k_layer2(
    const float* __restrict__ W2,
    const float* __restrict__ b2,
    float* __restrict__ out)
{
    const int e = blockIdx.y;
    const int cnt = g_cnt[e];
    const int base = blockIdx.x * 16;
    if (base >= cnt) return;

    __shared__ int rows[16];
    __shared__ __align__(16) float hs[16][64];    // [sample][f-chunk]
    __shared__ __align__(16) float w2s[64][68];   // [f][class], padded
    __shared__ float lg[16][68];                  // logits

    const int t = threadIdx.x;
    if (t < 16) {
        int p = base + t;
        rows[t] = (p < cnt) ? g_idx[e * BATCH + p] : -1;
    }
    __syncthreads();

    const int c = t & 63;         // class
    const int sg = t >> 6;        // sample group 0..3 (samples sg*4 .. sg*4+3)
    const int hs_s = t >> 4;      // sample for H loads
    const int hs_f = (t * 4) & 63;

    const int hrow = rows[hs_s];
    const float* hsrc = (hrow >= 0) ? g_H + (size_t)hrow * FDIM2 + hs_f : nullptr;

    float acc[4];
    {
        float bb = b2[e * NCLS + c];
        acc[0] = bb; acc[1] = bb; acc[2] = bb; acc[3] = bb;
    }
    const float* Wb = W2 + (size_t)e * FDIM2 * NCLS;

    for (int fc = 0; fc < FDIM2; fc += 64) {
        float4 hv = {0, 0, 0, 0};
        if (hsrc) hv = *reinterpret_cast<const float4*>(hsrc + fc);
        float4 wv[4];
#pragma unroll
        for (int r4 = 0; r4 < 4; r4++) {
            int idx = r4 * 1024 + t * 4;
            int f = idx >> 6, c4 = idx & 63;
            wv[r4] = *reinterpret_cast<const float4*>(Wb + (size_t)(fc + f) * NCLS + c4);
        }
        __syncthreads();
        *reinterpret_cast<float4*>(&hs[hs_s][hs_f]) = hv;
#pragma unroll
        for (int r4 = 0; r4 < 4; r4++) {
            int idx = r4 * 1024 + t * 4;
            int f = idx >> 6, c4 = idx & 63;
            *reinterpret_cast<float4*>(&w2s[f][c4]) = wv[r4];
        }
        __syncthreads();

#pragma unroll
        for (int f = 0; f < 64; f += 4) {
            float4 h0 = *reinterpret_cast<const float4*>(&hs[sg * 4 + 0][f]);
            float4 h1 = *reinterpret_cast<const float4*>(&hs[sg * 4 + 1][f]);
            float4 h2 = *reinterpret_cast<const float4*>(&hs[sg * 4 + 2][f]);
            float4 h3 = *reinterpret_cast<const float4*>(&hs[sg * 4 + 3][f]);
            float ha[4][4] = {{h0.x, h0.y, h0.z, h0.w},
                              {h1.x, h1.y, h1.z, h1.w},
                              {h2.x, h2.y, h2.z, h2.w},
                              {h3.x, h3.y, h3.z, h3.w}};
#pragma unroll
            for (int ff = 0; ff < 4; ff++) {
                float w = w2s[f + ff][c];
                acc[0] = fmaf(ha[0][ff], w, acc[0]);
                acc[1] = fmaf(ha[1][ff], w, acc[1]);
                acc[2] = fmaf(ha[2][ff], w, acc[2]);
                acc[3] = fmaf(ha[3][ff], w, acc[3]);
            }
        }
        __syncthreads();
    }

#pragma unroll
    for (int j = 0; j < 4; j++) lg[sg * 4 + j][c] = acc[j];
    __syncthreads();

    // softmax: warp w handles samples 2w, 2w+1; lane l owns classes l, l+32
    const int w = t >> 5, l = t & 31;
#pragma unroll
    for (int ss = 0; ss < 2; ss++) {
        int s = w * 2 + ss;
        int r = rows[s];
        if (r < 0) continue;  // uniform across warp
        float v0 = lg[s][l], v1 = lg[s][l + 32];
        float m = fmaxf(v0, v1);
#pragma unroll
        for (int off = 16; off >= 1; off >>= 1)
            m = fmaxf(m, __shfl_xor_sync(0xffffffffu, m, off));
        float e0 = __expf(v0 - m), e1 = __expf(v1 - m);
        float sm = e0 + e1;
#pragma unroll
        for (int off = 16; off >= 1; off >>= 1)
            sm += __shfl_xor_sync(0xffffffffu, sm, off);
        float inv = 1.0f / sm;
        out[(size_t)r * NCLS + l]      = e0 * inv;
        out[(size_t)r * NCLS + l + 32] = e1 * inv;
    }
}

// ---------------------------------------------------------------------------
extern "C" void kernel_launch(void* const* d_in, const int* in_sizes, int n_in,
                              void* d_out, int out_size)
{
    const int*   domain = (const int*)  d_in[0];
    const float* x      = (const float*)d_in[1];
    const float* W1     = (const float*)d_in[2];
    const float* b1     = (const float*)d_in[3];
    const float* W2     = (const float*)d_in[4];
    const float* b2     = (const float*)d_in[5];
    float* out = (float*)d_out;

    k_reset<<<1, 32>>>();
    k_bucket<<<BATCH / 256, 256>>>(domain);
    k_layer1<<<dim3(BATCH / 128, FDIM2 / 64, N_EXPERTS), 256>>>(x, W1, b1);
    k_layer2<<<dim3(BATCH / 16, N_EXPERTS), 256>>>(W2, b2, out);
}

// round 3
// speedup vs baseline: 1.5627x; 1.5627x over previous
#include <cuda_runtime.h>
#include <cuda_bf16.h>
#include <cstdint>

#define N_EXPERTS 8
#define FDIM1 1024
#define FDIM2 512
#define NCLS 64
#define BATCH 16384
#define APITCH 40   // smem row pitch in bf16 elems (32 + 8 pad: conflict-free ldmatrix)

// ---------------- scratch (static device arrays; allocation-free) ----------
__device__ __align__(16) __nv_bfloat16 g_W1t_hi[N_EXPERTS * FDIM2 * FDIM1];
__device__ __align__(16) __nv_bfloat16 g_W1t_lo[N_EXPERTS * FDIM2 * FDIM1];
__device__ __align__(16) __nv_bfloat16 g_W2t_hi[N_EXPERTS * NCLS * FDIM2];
__device__ __align__(16) __nv_bfloat16 g_W2t_lo[N_EXPERTS * NCLS * FDIM2];
__device__ __align__(16) __nv_bfloat16 g_H_hi[(size_t)BATCH * FDIM2];
__device__ __align__(16) __nv_bfloat16 g_H_lo[(size_t)BATCH * FDIM2];
__device__ int g_idx[N_EXPERTS * BATCH];
__device__ int g_cnt[N_EXPERTS];

// ---------------- helpers ---------------------------------------------------
__device__ __forceinline__ uint32_t smem_u32(const void* p) {
    uint32_t a;
    asm("{ .reg .u64 t; cvta.to.shared.u64 t, %1; cvt.u32.u64 %0, t; }"
        : "=r"(a) : "l"(p));
    return a;
}

__device__ __forceinline__ void ldsm4(uint32_t& r0, uint32_t& r1, uint32_t& r2,
                                      uint32_t& r3, uint32_t addr) {
    asm volatile("ldmatrix.sync.aligned.m8n8.x4.shared.b16 {%0,%1,%2,%3}, [%4];"
                 : "=r"(r0), "=r"(r1), "=r"(r2), "=r"(r3) : "r"(addr));
}

__device__ __forceinline__ void mma_bf16(float* c, const uint32_t* a,
                                         uint32_t b0, uint32_t b1) {
    asm volatile(
        "mma.sync.aligned.m16n8k16.row.col.f32.bf16.bf16.f32 "
        "{%0,%1,%2,%3}, {%4,%5,%6,%7}, {%8,%9}, {%0,%1,%2,%3};"
        : "+f"(c[0]), "+f"(c[1]), "+f"(c[2]), "+f"(c[3])
        : "r"(a[0]), "r"(a[1]), "r"(a[2]), "r"(a[3]), "r"(b0), "r"(b1));
}

__device__ __forceinline__ void split_bf(float v, unsigned short& h, unsigned short& l) {
    __nv_bfloat16 bh = __float2bfloat16(v);
    float rr = v - __bfloat162float(bh);
    h = __bfloat16_as_ushort(bh);
    l = __bfloat16_as_ushort(__float2bfloat16(rr));
}
__device__ __forceinline__ uint32_t pack2(float v0, float v1, uint32_t& lo) {
    unsigned short h0, l0, h1, l1;
    split_bf(v0, h0, l0);
    split_bf(v1, h1, l1);
    lo = (uint32_t)l0 | ((uint32_t)l1 << 16);
    return (uint32_t)h0 | ((uint32_t)h1 << 16);
}

// ---------------- small kernels ---------------------------------------------
__global__ void k_reset() {
    if (threadIdx.x < N_EXPERTS) g_cnt[threadIdx.x] = 0;
}

__global__ void k_bucket(const int* __restrict__ domain) {
    int i = blockIdx.x * blockDim.x + threadIdx.x;
    if (i < BATCH) {
        int e = domain[i];
        int p = atomicAdd(&g_cnt[e], 1);
        g_idx[e * BATCH + p] = i;
    }
}

// Transpose+convert W1 [e][k=1024][n=512] fp32 -> [e][n][k] bf16 hi/lo
__global__ void k_convW1(const float* __restrict__ src) {
    __shared__ float tile[32][33];
    int e = blockIdx.z;
    int kb = blockIdx.x * 32, nb = blockIdx.y * 32;
    const float* s = src + ((size_t)e * FDIM1 + kb) * FDIM2 + nb;
    int tx = threadIdx.x, ty = threadIdx.y;
#pragma unroll
    for (int i = 0; i < 32; i += 8) tile[ty + i][tx] = s[(size_t)(ty + i) * FDIM2 + tx];
    __syncthreads();
    size_t ob = ((size_t)e * FDIM2 + nb) * FDIM1 + kb;
#pragma unroll
    for (int i = 0; i < 32; i += 8) {
        float v = tile[tx][ty + i];
        unsigned short h, l;
        split_bf(v, h, l);
        g_W1t_hi[ob + (size_t)(ty + i) * FDIM1 + tx] = __ushort_as_bfloat16(h);
        g_W1t_lo[ob + (size_t)(ty + i) * FDIM1 + tx] = __ushort_as_bfloat16(l);
    }
}

// Transpose+convert W2 [e][k=512][n=64] fp32 -> [e][n][k] bf16 hi/lo
__global__ void k_convW2(const float* __restrict__ src) {
    __shared__ float tile[32][33];
    int e = blockIdx.z;
    int kb = blockIdx.x * 32, nb = blockIdx.y * 32;
    const float* s = src + ((size_t)e * FDIM2 + kb) * NCLS + nb;
    int tx = threadIdx.x, ty = threadIdx.y;
#pragma unroll
    for (int i = 0; i < 32; i += 8) tile[ty + i][tx] = s[(size_t)(ty + i) * NCLS + tx];
    __syncthreads();
    size_t ob = ((size_t)e * NCLS + nb) * FDIM2 + kb;
#pragma unroll
    for (int i = 0; i < 32; i += 8) {
        float v = tile[tx][ty + i];
        unsigned short h, l;
        split_bf(v, h, l);
        g_W2t_hi[ob + (size_t)(ty + i) * FDIM2 + tx] = __ushort_as_bfloat16(h);
        g_W2t_lo[ob + (size_t)(ty + i) * FDIM2 + tx] = __ushort_as_bfloat16(l);
    }
}

// ---------------- layer 1: bf16 mma.sync GEMM (3-pass hi/lo) ----------------
// CTA: 128 rows x 128 cols, K=1024 in 32 chunks of 32. 8 warps = 2(M) x 4(N).
__global__ __launch_bounds__(256) void k_gemm1(
    const float* __restrict__ x, const float* __restrict__ b1)
{
    const int e = blockIdx.z;
    const int cnt = g_cnt[e];
    const int mbase = blockIdx.x * 128;
    if (mbase >= cnt) return;
    const int nbase = blockIdx.y * 128;

    __shared__ int rows[128];
    __shared__ float bias[128];
    __shared__ __align__(16) __nv_bfloat16 sAh[128 * APITCH];
    __shared__ __align__(16) __nv_bfloat16 sAl[128 * APITCH];
    __shared__ __align__(16) __nv_bfloat16 sBh[128 * APITCH];
    __shared__ __align__(16) __nv_bfloat16 sBl[128 * APITCH];

    const int t = threadIdx.x;
    if (t < 128) {
        int p = mbase + t;
        rows[t] = (p < cnt) ? g_idx[e * BATCH + p] : -1;
        bias[t] = b1[e * FDIM2 + nbase + t];
    }
    __syncthreads();

    const int lr = t >> 1;
    const int lo16 = (t & 1) * 16;
    const int xr = rows[lr];
    const float* xp = (xr >= 0) ? x + (size_t)xr * FDIM1 + lo16 : nullptr;
    const __nv_bfloat16* wph = g_W1t_hi + (size_t)(e * FDIM2 + nbase + lr) * FDIM1 + lo16;
    const __nv_bfloat16* wpl = g_W1t_lo + (size_t)(e * FDIM2 + nbase + lr) * FDIM1 + lo16;

    float4 xa[4];
    uint4 wh2[2], wl2[2];

#define L1_LOAD(kc)                                                        \
    do {                                                                   \
        if (xp) {                                                          \
            const float4* s4 = (const float4*)(xp + (kc));                 \
            xa[0] = s4[0]; xa[1] = s4[1]; xa[2] = s4[2]; xa[3] = s4[3];    \
        } else {                                                           \
            xa[0] = xa[1] = xa[2] = xa[3] = make_float4(0.f, 0.f, 0.f, 0.f); \
        }                                                                  \
        wh2[0] = *(const uint4*)(wph + (kc));                              \
        wh2[1] = *(const uint4*)(wph + (kc) + 8);                          \
        wl2[0] = *(const uint4*)(wpl + (kc));                              \
        wl2[1] = *(const uint4*)(wpl + (kc) + 8);                          \
    } while (0)

    const int l = t & 31, wid = t >> 5;
    const int wm = (wid >> 2) * 64, wn = (wid & 3) * 32;
    const uint32_t aAh = smem_u32(sAh), aAl = smem_u32(sAl);
    const uint32_t aBh = smem_u32(sBh), aBl = smem_u32(sBl);
    const int lrow = l & 15;
    const int lk = (l >> 4) * 8;

    float acc[4][4][4];
#pragma unroll
    for (int i = 0; i < 4; i++)
#pragma unroll
        for (int j = 0; j < 4; j++)
#pragma unroll
            for (int q = 0; q < 4; q++) acc[i][j][q] = 0.f;

    L1_LOAD(0);

    for (int c = 0; c < 32; c++) {
        __syncthreads();
        // store prefetched regs into smem
#pragma unroll
        for (int q = 0; q < 4; q++) {
            uint32_t lo0, lo1, hi0, hi1;
            hi0 = pack2(((const float*)&xa[q])[0], ((const float*)&xa[q])[1], lo0);
            hi1 = pack2(((const float*)&xa[q])[2], ((const float*)&xa[q])[3], lo1);
            *(uint2*)(&sAh[lr * APITCH + lo16 + q * 4]) = make_uint2(hi0, hi1);
            *(uint2*)(&sAl[lr * APITCH + lo16 + q * 4]) = make_uint2(lo0, lo1);
        }
        *(uint2*)(&sBh[lr * APITCH + lo16 + 0])  = make_uint2(wh2[0].x, wh2[0].y);
        *(uint2*)(&sBh[lr * APITCH + lo16 + 4])  = make_uint2(wh2[0].z, wh2[0].w);
        *(uint2*)(&sBh[lr * APITCH + lo16 + 8])  = make_uint2(wh2[1].x, wh2[1].y);
        *(uint2*)(&sBh[lr * APITCH + lo16 + 12]) = make_uint2(wh2[1].z, wh2[1].w);
        *(uint2*)(&sBl[lr * APITCH + lo16 + 0])  = make_uint2(wl2[0].x, wl2[0].y);
        *(uint2*)(&sBl[lr * APITCH + lo16 + 4])  = make_uint2(wl2[0].z, wl2[0].w);
        *(uint2*)(&sBl[lr * APITCH + lo16 + 8])  = make_uint2(wl2[1].x, wl2[1].y);
        *(uint2*)(&sBl[lr * APITCH + lo16 + 12]) = make_uint2(wl2[1].z, wl2[1].w);
        __syncthreads();
        if (c < 31) L1_LOAD((c + 1) * 32);

#pragma unroll
        for (int ks = 0; ks < 32; ks += 16) {
            uint32_t ah[4][4], al[4][4], bh[4][2], bl[4][2];
#pragma unroll
            for (int mt = 0; mt < 4; mt++) {
                uint32_t off = ((wm + mt * 16 + lrow) * APITCH + ks + lk) * 2;
                ldsm4(ah[mt][0], ah[mt][1], ah[mt][2], ah[mt][3], aAh + off);
                ldsm4(al[mt][0], al[mt][1], al[mt][2], al[mt][3], aAl + off);
            }
#pragma unroll
            for (int bg = 0; bg < 2; bg++) {
                uint32_t off = ((wn + bg * 16 + lrow) * APITCH + ks + lk) * 2;
                uint32_t r0, r1, r2, r3;
                ldsm4(r0, r1, r2, r3, aBh + off);
                bh[2 * bg][0] = r0; bh[2 * bg + 1][0] = r1;
                bh[2 * bg][1] = r2; bh[2 * bg + 1][1] = r3;
                ldsm4(r0, r1, r2, r3, aBl + off);
                bl[2 * bg][0] = r0; bl[2 * bg + 1][0] = r1;
                bl[2 * bg][1] = r2; bl[2 * bg + 1][1] = r3;
            }
#pragma unroll
            for (int mt = 0; mt < 4; mt++)
#pragma unroll
                for (int nt = 0; nt < 4; nt++) {
                    mma_bf16(acc[mt][nt], ah[mt], bh[nt][0], bh[nt][1]);
                    mma_bf16(acc[mt][nt], ah[mt], bl[nt][0], bl[nt][1]);
                    mma_bf16(acc[mt][nt], al[mt], bh[nt][0], bh[nt][1]);
                }
        }
    }

    // epilogue: + bias, relu, split to bf16 hi/lo, scatter to g_H
#pragma unroll
    for (int mt = 0; mt < 4; mt++) {
        int r0i = wm + mt * 16 + (l >> 2);
        int ra = rows[r0i], rb = rows[r0i + 8];
#pragma unroll
        for (int nt = 0; nt < 4; nt++) {
            int cl = wn + nt * 8 + (l & 3) * 2;
            float b0 = bias[cl], b1v = bias[cl + 1];
            if (ra >= 0) {
                uint32_t lo, hi = pack2(fmaxf(acc[mt][nt][0] + b0, 0.f),
                                        fmaxf(acc[mt][nt][1] + b1v, 0.f), lo);
                size_t off = (size_t)ra * FDIM2 + nbase + cl;
                *(uint32_t*)(&g_H_hi[off]) = hi;
                *(uint32_t*)(&g_H_lo[off]) = lo;
            }
            if (rb >= 0) {
                uint32_t lo, hi = pack2(fmaxf(acc[mt][nt][2] + b0, 0.f),
                                        fmaxf(acc[mt][nt][3] + b1v, 0.f), lo);
                size_t off = (size_t)rb * FDIM2 + nbase + cl;
                *(uint32_t*)(&g_H_hi[off]) = hi;
                *(uint32_t*)(&g_H_lo[off]) = lo;
            }
        }
    }
#undef L1_LOAD
}

// ---------------- layer 2: bf16 mma.sync GEMM + softmax ---------------------
// CTA: 128 rows x 64 cols, K=512 in 16 chunks of 32. 8 warps = 4(M) x 2(N).
#define SM2_AH 0
#define SM2_AL 10240
#define SM2_BH 20480
#define SM2_BL 25600
#define SM2_SZ 34816  /* union with logits: 128 x 68 floats */

__global__ __launch_bounds__(256) void k_gemm2(
    const float* __restrict__ b2, float* __restrict__ out)
{
    const int e = blockIdx.y;
    const int cnt = g_cnt[e];
    const int mbase = blockIdx.x * 128;
    if (mbase >= cnt) return;

    __shared__ int rows[128];
    __shared__ float b2s[64];
    __shared__ __align__(16) char sm[SM2_SZ];

    const int t = threadIdx.x;
    if (t < 128) {
        int p = mbase + t;
        rows[t] = (p < cnt) ? g_idx[e * BATCH + p] : -1;
    }
    if (t < 64) b2s[t] = b2[e * NCLS + t];
    __syncthreads();

    __nv_bfloat16* sAh = (__nv_bfloat16*)(sm + SM2_AH);
    __nv_bfloat16* sAl = (__nv_bfloat16*)(sm + SM2_AL);
    __nv_bfloat16* sBh = (__nv_bfloat16*)(sm + SM2_BH);
    __nv_bfloat16* sBl = (__nv_bfloat16*)(sm + SM2_BL);

    const int lr = t >> 1;
    const int lo16 = (t & 1) * 16;
    const int hr = rows[lr];
    const __nv_bfloat16* hph = (hr >= 0) ? g_H_hi + (size_t)hr * FDIM2 + lo16 : nullptr;
    const __nv_bfloat16* hpl = (hr >= 0) ? g_H_lo + (size_t)hr * FDIM2 + lo16 : nullptr;
    // B loads: threads 0-127 load hi, 128-255 load lo (64 rows x 32 bf16 each)
    const int bt = t & 127;
    const int br = bt >> 1, blo16 = (bt & 1) * 16;
    const __nv_bfloat16* wp =
        ((t < 128) ? g_W2t_hi : g_W2t_lo) + (size_t)(e * NCLS + br) * FDIM2 + blo16;
    __nv_bfloat16* sB = (t < 128) ? sBh : sBl;

    uint4 ha[2], la[2], wb[2];

#define L2_LOAD(kc)                                                       \
    do {                                                                  \
        if (hph) {                                                        \
            ha[0] = *(const uint4*)(hph + (kc));                          \
            ha[1] = *(const uint4*)(hph + (kc) + 8);                      \
            la[0] = *(const uint4*)(hpl + (kc));                          \
            la[1] = *(const uint4*)(hpl + (kc) + 8);                      \
        } else {                                                          \
            ha[0] = ha[1] = la[0] = la[1] = make_uint4(0, 0, 0, 0);       \
        }                                                                 \
        wb[0] = *(const uint4*)(wp + (kc));                               \
        wb[1] = *(const uint4*)(wp + (kc) + 8);                           \
    } while (0)

    const int l = t & 31, wid = t >> 5;
    const int wm = (wid >> 1) * 32, wn = (wid & 1) * 32;
    const uint32_t aAh = smem_u32(sAh), aAl = smem_u32(sAl);
    const uint32_t aBh = smem_u32(sBh), aBl = smem_u32(sBl);
    const int lrow = l & 15;
    const int lk = (l >> 4) * 8;

    float acc[2][4][4];
#pragma unroll
    for (int i = 0; i < 2; i++)
#pragma unroll
        for (int j = 0; j < 4; j++)
#pragma unroll
            for (int q = 0; q < 4; q++) acc[i][j][q] = 0.f;

    L2_LOAD(0);

    for (int c = 0; c < 16; c++) {
        __syncthreads();
        *(uint2*)(&sAh[lr * APITCH + lo16 + 0])  = make_uint2(ha[0].x, ha[0].y);
        *(uint2*)(&sAh[lr * APITCH + lo16 + 4])  = make_uint2(ha[0].z, ha[0].w);
        *(uint2*)(&sAh[lr * APITCH + lo16 + 8])  = make_uint2(ha[1].x, ha[1].y);
        *(uint2*)(&sAh[lr * APITCH + lo16 + 12]) = make_uint2(ha[1].z, ha[1].w);
        *(uint2*)(&sAl[lr * APITCH + lo16 + 0])  = make_uint2(la[0].x, la[0].y);
        *(uint2*)(&sAl[lr * APITCH + lo16 + 4])  = make_uint2(la[0].z, la[0].w);
        *(uint2*)(&sAl[lr * APITCH + lo16 + 8])  = make_uint2(la[1].x, la[1].y);
        *(uint2*)(&sAl[lr * APITCH + lo16 + 12]) = make_uint2(la[1].z, la[1].w);
        *(uint2*)(&sB[br * APITCH + blo16 + 0])  = make_uint2(wb[0].x, wb[0].y);
        *(uint2*)(&sB[br * APITCH + blo16 + 4])  = make_uint2(wb[0].z, wb[0].w);
        *(uint2*)(&sB[br * APITCH + blo16 + 8])  = make_uint2(wb[1].x, wb[1].y);
        *(uint2*)(&sB[br * APITCH + blo16 + 12]) = make_uint2(wb[1].z, wb[1].w);
        __syncthreads();
        if (c < 15) L2_LOAD((c + 1) * 32);

#pragma unroll
        for (int ks = 0; ks < 32; ks += 16) {
            uint32_t ah[2][4], al[2][4], bh[4][2], bl[4][2];
#pragma unroll
            for (int mt = 0; mt < 2; mt++) {
                uint32_t off = ((wm + mt * 16 + lrow) * APITCH + ks + lk) * 2;
                ldsm4(ah[mt][0], ah[mt][1], ah[mt][2], ah[mt][3], aAh + off);
                ldsm4(al[mt][0], al[mt][1], al[mt][2], al[mt][3], aAl + off);
            }
#pragma unroll
            for (int bg = 0; bg < 2; bg++) {
                uint32_t off = ((wn + bg * 16 + lrow) * APITCH + ks + lk) * 2;
                uint32_t r0, r1, r2, r3;
                ldsm4(r0, r1, r2, r3, aBh + off);
                bh[2 * bg][0] = r0; bh[2 * bg + 1][0] = r1;
                bh[2 * bg][1] = r2; bh[2 * bg + 1][1] = r3;
                ldsm4(r0, r1, r2, r3, aBl + off);
                bl[2 * bg][0] = r0; bl[2 * bg + 1][0] = r1;
                bl[2 * bg][1] = r2; bl[2 * bg + 1][1] = r3;
            }
#pragma unroll
            for (int mt = 0; mt < 2; mt++)
#pragma unroll
                for (int nt = 0; nt < 4; nt++) {
                    mma_bf16(acc[mt][nt], ah[mt], bh[nt][0], bh[nt][1]);
                    mma_bf16(acc[mt][nt], ah[mt], bl[nt][0], bl[nt][1]);
                    mma_bf16(acc[mt][nt], al[mt], bh[nt][0], bh[nt][1]);
                }
        }
    }

    // logits -> smem (union over A/B buffers), then per-thread softmax
    __syncthreads();
    float* lg = (float*)sm;  // [128][68]
#pragma unroll
    for (int mt = 0; mt < 2; mt++) {
        int r0i = wm + mt * 16 + (l >> 2);
#pragma unroll
        for (int nt = 0; nt < 4; nt++) {
            int cl = wn + nt * 8 + (l & 3) * 2;
            lg[r0i * 68 + cl]           = acc[mt][nt][0];
            lg[r0i * 68 + cl + 1]       = acc[mt][nt][1];
            lg[(r0i + 8) * 68 + cl]     = acc[mt][nt][2];
            lg[(r0i + 8) * 68 + cl + 1] = acc[mt][nt][3];
        }
    }
    __syncthreads();

    if (t < 128) {
        int r = rows[t];
        if (r >= 0) {
            float v[64];
            float mx = -3.4e38f;
#pragma unroll
            for (int j = 0; j < 64; j++) {
                v[j] = lg[t * 68 + j] + b2s[j];
                mx = fmaxf(mx, v[j]);
            }
            float s = 0.f;
#pragma unroll
            for (int j = 0; j < 64; j++) {
                v[j] = __expf(v[j] - mx);
                s += v[j];
            }
            float inv = 1.0f / s;
            float4* op = (float4*)(out + (size_t)r * NCLS);
#pragma unroll
            for (int q = 0; q < 16; q++)
                op[q] = make_float4(v[4 * q] * inv, v[4 * q + 1] * inv,
                                    v[4 * q + 2] * inv, v[4 * q + 3] * inv);
        }
    }
#undef L2_LOAD
}

// ---------------------------------------------------------------------------
extern "C" void kernel_launch(void* const* d_in, const int* in_sizes, int n_in,
                              void* d_out, int out_size)
{
    const int*   domain = (const int*)  d_in[0];
    const float* x      = (const float*)d_in[1];
    const float* W1     = (const float*)d_in[2];
    const float* b1     = (const float*)d_in[3];
    const float* W2     = (const float*)d_in[4];
    const float* b2     = (const float*)d_in[5];
    float* out = (float*)d_out;

    k_reset<<<1, 32>>>();
    k_bucket<<<BATCH / 256, 256>>>(domain);
    k_convW1<<<dim3(FDIM1 / 32, FDIM2 / 32, N_EXPERTS), dim3(32, 8)>>>(W1);
    k_convW2<<<dim3(FDIM2 / 32, NCLS / 32, N_EXPERTS), dim3(32, 8)>>>(W2);
    k_gemm1<<<dim3(BATCH / 128, FDIM2 / 128, N_EXPERTS), 256>>>(x, b1);
    k_gemm2<<<dim3(BATCH / 128, N_EXPERTS), 256>>>(b2, out);
}

// round 4
// speedup vs baseline: 2.1281x; 1.3617x over previous
#include <cuda_runtime.h>
#include <cuda_fp16.h>
#include <cstdint>

#define N_EXPERTS 8
#define FDIM1 1024
#define FDIM2 512
#define NCLS 64
#define BATCH 16384
#define APITCH 40   // smem row pitch in fp16 elems (32 + 8 pad: conflict-free ldmatrix)

// ---------------- scratch (static device arrays; allocation-free) ----------
__device__ __align__(16) __half g_W1t_hi[N_EXPERTS * FDIM2 * FDIM1];
__device__ __align__(16) __half g_W1t_lo[N_EXPERTS * FDIM2 * FDIM1];
__device__ __align__(16) __half g_W2t_hi[N_EXPERTS * NCLS * FDIM2];
__device__ __align__(16) __half g_W2t_lo[N_EXPERTS * NCLS * FDIM2];
__device__ __align__(16) __half g_H[(size_t)BATCH * FDIM2];
__device__ int g_idx[N_EXPERTS * BATCH];
__device__ int g_cnt[N_EXPERTS];

// ---------------- helpers ---------------------------------------------------
__device__ __forceinline__ uint32_t smem_u32(const void* p) {
    uint32_t a;
    asm("{ .reg .u64 t; cvta.to.shared.u64 t, %1; cvt.u32.u64 %0, t; }"
        : "=r"(a) : "l"(p));
    return a;
}

__device__ __forceinline__ void ldsm4(uint32_t& r0, uint32_t& r1, uint32_t& r2,
                                      uint32_t& r3, uint32_t addr) {
    asm volatile("ldmatrix.sync.aligned.m8n8.x4.shared.b16 {%0,%1,%2,%3}, [%4];"
                 : "=r"(r0), "=r"(r1), "=r"(r2), "=r"(r3) : "r"(addr));
}

__device__ __forceinline__ void mma_fp16(float* c, const uint32_t* a,
                                         uint32_t b0, uint32_t b1) {
    asm volatile(
        "mma.sync.aligned.m16n8k16.row.col.f32.f16.f16.f32 "
        "{%0,%1,%2,%3}, {%4,%5,%6,%7}, {%8,%9}, {%0,%1,%2,%3};"
        : "+f"(c[0]), "+f"(c[1]), "+f"(c[2]), "+f"(c[3])
        : "r"(a[0]), "r"(a[1]), "r"(a[2]), "r"(a[3]), "r"(b0), "r"(b1));
}

__device__ __forceinline__ uint32_t packh2(float v0, float v1) {
    __half2 h = __floats2half2_rn(v0, v1);
    return *(uint32_t*)&h;
}

// ---------------- small kernels ---------------------------------------------
__global__ void k_reset() {
    if (threadIdx.x < N_EXPERTS) g_cnt[threadIdx.x] = 0;
}

__global__ void k_bucket(const int* __restrict__ domain) {
    int i = blockIdx.x * blockDim.x + threadIdx.x;
    if (i < BATCH) {
        int e = domain[i];
        int p = atomicAdd(&g_cnt[e], 1);
        g_idx[e * BATCH + p] = i;
    }
}

// Transpose+convert W1 [e][k=1024][n=512] fp32 -> [e][n][k] fp16 hi/lo
__global__ void k_convW1(const float* __restrict__ src) {
    __shared__ float tile[32][33];
    int e = blockIdx.z;
    int kb = blockIdx.x * 32, nb = blockIdx.y * 32;
    const float* s = src + ((size_t)e * FDIM1 + kb) * FDIM2 + nb;
    int tx = threadIdx.x, ty = threadIdx.y;
#pragma unroll
    for (int i = 0; i < 32; i += 8) tile[ty + i][tx] = s[(size_t)(ty + i) * FDIM2 + tx];
    __syncthreads();
    size_t ob = ((size_t)e * FDIM2 + nb) * FDIM1 + kb;
#pragma unroll
    for (int i = 0; i < 32; i += 8) {
        float v = tile[tx][ty + i];
        __half h = __float2half_rn(v);
        __half l = __float2half_rn(v - __half2float(h));
        g_W1t_hi[ob + (size_t)(ty + i) * FDIM1 + tx] = h;
        g_W1t_lo[ob + (size_t)(ty + i) * FDIM1 + tx] = l;
    }
}

// Transpose+convert W2 [e][k=512][n=64] fp32 -> [e][n][k] fp16 hi/lo
__global__ void k_convW2(const float* __restrict__ src) {
    __shared__ float tile[32][33];
    int e = blockIdx.z;
    int kb = blockIdx.x * 32, nb = blockIdx.y * 32;
    const float* s = src + ((size_t)e * FDIM2 + kb) * NCLS + nb;
    int tx = threadIdx.x, ty = threadIdx.y;
#pragma unroll
    for (int i = 0; i < 32; i += 8) tile[ty + i][tx] = s[(size_t)(ty + i) * NCLS + tx];
    __syncthreads();
    size_t ob = ((size_t)e * NCLS + nb) * FDIM2 + kb;
#pragma unroll
    for (int i = 0; i < 32; i += 8) {
        float v = tile[tx][ty + i];
        __half h = __float2half_rn(v);
        __half l = __float2half_rn(v - __half2float(h));
        g_W2t_hi[ob + (size_t)(ty + i) * FDIM2 + tx] = h;
        g_W2t_lo[ob + (size_t)(ty + i) * FDIM2 + tx] = l;
    }
}

// ---------------- layer 1: fp16 mma.sync GEMM (2-pass: A*Bh + A*Bl) ---------
// CTA: 128 rows x 128 cols, K=1024 in 32 chunks of 32. 8 warps = 2(M) x 4(N).
__global__ __launch_bounds__(256) void k_gemm1(
    const float* __restrict__ x, const float* __restrict__ b1)
{
    const int e = blockIdx.z;
    const int cnt = g_cnt[e];
    const int mbase = blockIdx.x * 128;
    if (mbase >= cnt) return;
    const int nbase = blockIdx.y * 128;

    __shared__ int rows[128];
    __shared__ float bias[128];
    __shared__ __align__(16) __half sA[128 * APITCH];
    __shared__ __align__(16) __half sBh[128 * APITCH];
    __shared__ __align__(16) __half sBl[128 * APITCH];

    const int t = threadIdx.x;
    if (t < 128) {
        int p = mbase + t;
        rows[t] = (p < cnt) ? g_idx[e * BATCH + p] : -1;
        bias[t] = b1[e * FDIM2 + nbase + t];
    }
    __syncthreads();

    const int lr = t >> 1;
    const int lo16 = (t & 1) * 16;
    const int xr = rows[lr];
    const float* xp = (xr >= 0) ? x + (size_t)xr * FDIM1 + lo16 : nullptr;
    const __half* wph = g_W1t_hi + (size_t)(e * FDIM2 + nbase + lr) * FDIM1 + lo16;
    const __half* wpl = g_W1t_lo + (size_t)(e * FDIM2 + nbase + lr) * FDIM1 + lo16;

    float4 xa[4];
    uint4 wh2[2], wl2[2];

#define L1_LOAD(kc)                                                        \
    do {                                                                   \
        if (xp) {                                                          \
            const float4* s4 = (const float4*)(xp + (kc));                 \
            xa[0] = s4[0]; xa[1] = s4[1]; xa[2] = s4[2]; xa[3] = s4[3];    \
        } else {                                                           \
            xa[0] = xa[1] = xa[2] = xa[3] = make_float4(0.f, 0.f, 0.f, 0.f); \
        }                                                                  \
        wh2[0] = *(const uint4*)(wph + (kc));                              \
        wh2[1] = *(const uint4*)(wph + (kc) + 8);                          \
        wl2[0] = *(const uint4*)(wpl + (kc));                              \
        wl2[1] = *(const uint4*)(wpl + (kc) + 8);                          \
    } while (0)

    const int l = t & 31, wid = t >> 5;
    const int wm = (wid >> 2) * 64, wn = (wid & 3) * 32;
    const uint32_t aA = smem_u32(sA);
    const uint32_t aBh = smem_u32(sBh), aBl = smem_u32(sBl);
    const int lrow = l & 15;
    const int lk = (l >> 4) * 8;

    float acc[4][4][4];
#pragma unroll
    for (int i = 0; i < 4; i++)
#pragma unroll
        for (int j = 0; j < 4; j++)
#pragma unroll
            for (int q = 0; q < 4; q++) acc[i][j][q] = 0.f;

    L1_LOAD(0);

    for (int c = 0; c < 32; c++) {
        __syncthreads();
        // store prefetched regs into smem (x converted to single fp16)
        {
            uint32_t p0 = packh2(xa[0].x, xa[0].y), p1 = packh2(xa[0].z, xa[0].w);
            uint32_t p2 = packh2(xa[1].x, xa[1].y), p3 = packh2(xa[1].z, xa[1].w);
            uint32_t p4 = packh2(xa[2].x, xa[2].y), p5 = packh2(xa[2].z, xa[2].w);
            uint32_t p6 = packh2(xa[3].x, xa[3].y), p7 = packh2(xa[3].z, xa[3].w);
            *(uint4*)(&sA[lr * APITCH + lo16])     = make_uint4(p0, p1, p2, p3);
            *(uint4*)(&sA[lr * APITCH + lo16 + 8]) = make_uint4(p4, p5, p6, p7);
        }
        *(uint4*)(&sBh[lr * APITCH + lo16])     = wh2[0];
        *(uint4*)(&sBh[lr * APITCH + lo16 + 8]) = wh2[1];
        *(uint4*)(&sBl[lr * APITCH + lo16])     = wl2[0];
        *(uint4*)(&sBl[lr * APITCH + lo16 + 8]) = wl2[1];
        __syncthreads();
        if (c < 31) L1_LOAD((c + 1) * 32);

#pragma unroll
        for (int ks = 0; ks < 32; ks += 16) {
            uint32_t ah[4][4], bh[4][2], bl[4][2];
#pragma unroll
            for (int mt = 0; mt < 4; mt++) {
                uint32_t off = ((wm + mt * 16 + lrow) * APITCH + ks + lk) * 2;
                ldsm4(ah[mt][0], ah[mt][1], ah[mt][2], ah[mt][3], aA + off);
            }
#pragma unroll
            for (int bg = 0; bg < 2; bg++) {
                uint32_t off = ((wn + bg * 16 + lrow) * APITCH + ks + lk) * 2;
                uint32_t r0, r1, r2, r3;
                ldsm4(r0, r1, r2, r3, aBh + off);
                bh[2 * bg][0] = r0; bh[2 * bg + 1][0] = r1;
                bh[2 * bg][1] = r2; bh[2 * bg + 1][1] = r3;
                ldsm4(r0, r1, r2, r3, aBl + off);
                bl[2 * bg][0] = r0; bl[2 * bg + 1][0] = r1;
                bl[2 * bg][1] = r2; bl[2 * bg + 1][1] = r3;
            }
#pragma unroll
            for (int mt = 0; mt < 4; mt++)
#pragma unroll
                for (int nt = 0; nt < 4; nt++) {
                    mma_fp16(acc[mt][nt], ah[mt], bh[nt][0], bh[nt][1]);
                    mma_fp16(acc[mt][nt], ah[mt], bl[nt][0], bl[nt][1]);
                }
        }
    }

    // epilogue: + bias, relu, fp16, scatter to g_H
#pragma unroll
    for (int mt = 0; mt < 4; mt++) {
        int r0i = wm + mt * 16 + (l >> 2);
        int ra = rows[r0i], rb = rows[r0i + 8];
#pragma unroll
        for (int nt = 0; nt < 4; nt++) {
            int cl = wn + nt * 8 + (l & 3) * 2;
            float b0 = bias[cl], b1v = bias[cl + 1];
            if (ra >= 0) {
                uint32_t h = packh2(fmaxf(acc[mt][nt][0] + b0, 0.f),
                                    fmaxf(acc[mt][nt][1] + b1v, 0.f));
                *(uint32_t*)(&g_H[(size_t)ra * FDIM2 + nbase + cl]) = h;
            }
            if (rb >= 0) {
                uint32_t h = packh2(fmaxf(acc[mt][nt][2] + b0, 0.f),
                                    fmaxf(acc[mt][nt][3] + b1v, 0.f));
                *(uint32_t*)(&g_H[(size_t)rb * FDIM2 + nbase + cl]) = h;
            }
        }
    }
#undef L1_LOAD
}

// ---------------- layer 2: fp16 mma.sync GEMM + softmax ---------------------
// CTA: 128 rows x 64 cols, K=512 in 16 chunks of 32. 8 warps = 4(M) x 2(N).
#define SM2_A 0
#define SM2_BH 10240
#define SM2_BL 15360
#define SM2_SZ 34816  /* union with logits: 128 x 68 floats */

__global__ __launch_bounds__(256) void k_gemm2(
    const float* __restrict__ b2, float* __restrict__ out)
{
    const int e = blockIdx.y;
    const int cnt = g_cnt[e];
    const int mbase = blockIdx.x * 128;
    if (mbase >= cnt) return;

    __shared__ int rows[128];
    __shared__ float b2s[64];
    __shared__ __align__(16) char sm[SM2_SZ];

    const int t = threadIdx.x;
    if (t < 128) {
        int p = mbase + t;
        rows[t] = (p < cnt) ? g_idx[e * BATCH + p] : -1;
    }
    if (t < 64) b2s[t] = b2[e * NCLS + t];
    __syncthreads();

    __half* sA = (__half*)(sm + SM2_A);
    __half* sBh = (__half*)(sm + SM2_BH);
    __half* sBl = (__half*)(sm + SM2_BL);

    const int lr = t >> 1;
    const int lo16 = (t & 1) * 16;
    const int hr = rows[lr];
    const __half* hp = (hr >= 0) ? g_H + (size_t)hr * FDIM2 + lo16 : nullptr;
    // B loads: threads 0-127 load hi, 128-255 load lo (64 rows x 32 fp16 each)
    const int bt = t & 127;
    const int br = bt >> 1, blo16 = (bt & 1) * 16;
    const __half* wp =
        ((t < 128) ? g_W2t_hi : g_W2t_lo) + (size_t)(e * NCLS + br) * FDIM2 + blo16;
    __half* sB = (t < 128) ? sBh : sBl;

    uint4 ha[2], wb[2];

#define L2_LOAD(kc)                                                       \
    do {                                                                  \
        if (hp) {                                                         \
            ha[0] = *(const uint4*)(hp + (kc));                           \
            ha[1] = *(const uint4*)(hp + (kc) + 8);                       \
        } else {                                                          \
            ha[0] = ha[1] = make_uint4(0, 0, 0, 0);                       \
        }                                                                 \
        wb[0] = *(const uint4*)(wp + (kc));                               \
        wb[1] = *(const uint4*)(wp + (kc) + 8);                           \
    } while (0)

    const int l = t & 31, wid = t >> 5;
    const int wm = (wid >> 1) * 32, wn = (wid & 1) * 32;
    const uint32_t aA = smem_u32(sA);
    const uint32_t aBh = smem_u32(sBh), aBl = smem_u32(sBl);
    const int lrow = l & 15;
    const int lk = (l >> 4) * 8;

    float acc[2][4][4];
#pragma unroll
    for (int i = 0; i < 2; i++)
#pragma unroll
        for (int j = 0; j < 4; j++)
#pragma unroll
            for (int q = 0; q < 4; q++) acc[i][j][q] = 0.f;

    L2_LOAD(0);

    for (int c = 0; c < 16; c++) {
        __syncthreads();
        *(uint4*)(&sA[lr * APITCH + lo16])      = ha[0];
        *(uint4*)(&sA[lr * APITCH + lo16 + 8])  = ha[1];
        *(uint4*)(&sB[br * APITCH + blo16])     = wb[0];
        *(uint4*)(&sB[br * APITCH + blo16 + 8]) = wb[1];
        __syncthreads();
        if (c < 15) L2_LOAD((c + 1) * 32);

#pragma unroll
        for (int ks = 0; ks < 32; ks += 16) {
            uint32_t ah[2][4], bh[4][2], bl[4][2];
#pragma unroll
            for (int mt = 0; mt < 2; mt++) {
                uint32_t off = ((wm + mt * 16 + lrow) * APITCH + ks + lk) * 2;
                ldsm4(ah[mt][0], ah[mt][1], ah[mt][2], ah[mt][3], aA + off);
            }
#pragma unroll
            for (int bg = 0; bg < 2; bg++) {
                uint32_t off = ((wn + bg * 16 + lrow) * APITCH + ks + lk) * 2;
                uint32_t r0, r1, r2, r3;
                ldsm4(r0, r1, r2, r3, aBh + off);
                bh[2 * bg][0] = r0; bh[2 * bg + 1][0] = r1;
                bh[2 * bg][1] = r2; bh[2 * bg + 1][1] = r3;
                ldsm4(r0, r1, r2, r3, aBl + off);
                bl[2 * bg][0] = r0; bl[2 * bg + 1][0] = r1;
                bl[2 * bg][1] = r2; bl[2 * bg + 1][1] = r3;
            }
#pragma unroll
            for (int mt = 0; mt < 2; mt++)
#pragma unroll
                for (int nt = 0; nt < 4; nt++) {
                    mma_fp16(acc[mt][nt], ah[mt], bh[nt][0], bh[nt][1]);
                    mma_fp16(acc[mt][nt], ah[mt], bl[nt][0], bl[nt][1]);
                }
        }
    }

    // logits -> smem (union over A/B buffers), then per-thread softmax
    __syncthreads();
    float* lg = (float*)sm;  // [128][68]
#pragma unroll
    for (int mt = 0; mt < 2; mt++) {
        int r0i = wm + mt * 16 + (l >> 2);
#pragma unroll
        for (int nt = 0; nt < 4; nt++) {
            int cl = wn + nt * 8 + (l & 3) * 2;
            lg[r0i * 68 + cl]           = acc[mt][nt][0];
            lg[r0i * 68 + cl + 1]       = acc[mt][nt][1];
            lg[(r0i + 8) * 68 + cl]     = acc[mt][nt][2];
            lg[(r0i + 8) * 68 + cl + 1] = acc[mt][nt][3];
        }
    }
    __syncthreads();

    if (t < 128) {
        int r = rows[t];
        if (r >= 0) {
            float v[64];
            float mx = -3.4e38f;
#pragma unroll
            for (int j = 0; j < 64; j++) {
                v[j] = lg[t * 68 + j] + b2s[j];
                mx = fmaxf(mx, v[j]);
            }
            float s = 0.f;
#pragma unroll
            for (int j = 0; j < 64; j++) {
                v[j] = __expf(v[j] - mx);
                s += v[j];
            }
            float inv = 1.0f / s;
            float4* op = (float4*)(out + (size_t)r * NCLS);
#pragma unroll
            for (int q = 0; q < 16; q++)
                op[q] = make_float4(v[4 * q] * inv, v[4 * q + 1] * inv,
                                    v[4 * q + 2] * inv, v[4 * q + 3] * inv);
        }
    }
#undef L2_LOAD
}

// ---------------------------------------------------------------------------
extern "C" void kernel_launch(void* const* d_in, const int* in_sizes, int n_in,
                              void* d_out, int out_size)
{
    const int*   domain = (const int*)  d_in[0];
    const float* x      = (const float*)d_in[1];
    const float* W1     = (const float*)d_in[2];
    const float* b1     = (const float*)d_in[3];
    const float* W2     = (const float*)d_in[4];
    const float* b2     = (const float*)d_in[5];
    float* out = (float*)d_out;

    k_reset<<<1, 32>>>();
    k_bucket<<<BATCH / 256, 256>>>(domain);
    k_convW1<<<dim3(FDIM1 / 32, FDIM2 / 32, N_EXPERTS), dim3(32, 8)>>>(W1);
    k_convW2<<<dim3(FDIM2 / 32, NCLS / 32, N_EXPERTS), dim3(32, 8)>>>(W2);
    k_gemm1<<<dim3(BATCH / 128, FDIM2 / 128, N_EXPERTS), 256>>>(x, b1);
    k_gemm2<<<dim3(BATCH / 128, N_EXPERTS), 256>>>(b2, out);
}

// round 5
// speedup vs baseline: 2.5744x; 1.2097x over previous
#include <cuda_runtime.h>
#include <cuda_fp16.h>
#include <cstdint>

#define N_EXPERTS 8
#define FDIM1 1024
#define FDIM2 512
#define NCLS 64
#define BATCH 16384
#define APITCH 40   // smem row pitch in fp16 elems (32 + 8 pad: conflict-free ldmatrix)

// ---------------- scratch (static device arrays; allocation-free) ----------
__device__ __align__(16) __half g_W1t_hi[N_EXPERTS * FDIM2 * FDIM1];
__device__ __align__(16) __half g_W1t_lo[N_EXPERTS * FDIM2 * FDIM1];
__device__ __align__(16) __half g_W2t_hi[N_EXPERTS * NCLS * FDIM2];
__device__ __align__(16) __half g_W2t_lo[N_EXPERTS * NCLS * FDIM2];
__device__ __align__(16) __half g_H[(size_t)BATCH * FDIM2];
__device__ int g_idx[N_EXPERTS * BATCH];
__device__ int g_cnt[N_EXPERTS];

// ---------------- helpers ---------------------------------------------------
__device__ __forceinline__ uint32_t smem_u32(const void* p) {
    uint32_t a;
    asm("{ .reg .u64 t; cvta.to.shared.u64 t, %1; cvt.u32.u64 %0, t; }"
        : "=r"(a) : "l"(p));
    return a;
}

__device__ __forceinline__ void ldsm4(uint32_t& r0, uint32_t& r1, uint32_t& r2,
                                      uint32_t& r3, uint32_t addr) {
    asm volatile("ldmatrix.sync.aligned.m8n8.x4.shared.b16 {%0,%1,%2,%3}, [%4];"
                 : "=r"(r0), "=r"(r1), "=r"(r2), "=r"(r3) : "r"(addr));
}

__device__ __forceinline__ void mma_fp16(float* c, const uint32_t* a,
                                         uint32_t b0, uint32_t b1) {
    asm volatile(
        "mma.sync.aligned.m16n8k16.row.col.f32.f16.f16.f32 "
        "{%0,%1,%2,%3}, {%4,%5,%6,%7}, {%8,%9}, {%0,%1,%2,%3};"
        : "+f"(c[0]), "+f"(c[1]), "+f"(c[2]), "+f"(c[3])
        : "r"(a[0]), "r"(a[1]), "r"(a[2]), "r"(a[3]), "r"(b0), "r"(b1));
}

__device__ __forceinline__ void cpasync16(uint32_t dst, const void* src) {
    asm volatile("cp.async.ca.shared.global [%0], [%1], 16;"
                 :: "r"(dst), "l"(src) : "memory");
}
#define CP_COMMIT() asm volatile("cp.async.commit_group;" ::: "memory")
#define CP_WAIT(n) asm volatile("cp.async.wait_group %0;" ::"n"(n) : "memory")

__device__ __forceinline__ uint32_t packh2(float v0, float v1) {
    __half2 h = __floats2half2_rn(v0, v1);
    return *(uint32_t*)&h;
}

// ---------------- small kernels ---------------------------------------------
__global__ void k_reset() {
    if (threadIdx.x < N_EXPERTS) g_cnt[threadIdx.x] = 0;
}

__global__ void k_bucket(const int* __restrict__ domain) {
    int i = blockIdx.x * blockDim.x + threadIdx.x;
    if (i < BATCH) {
        int e = domain[i];
        int p = atomicAdd(&g_cnt[e], 1);
        g_idx[e * BATCH + p] = i;
    }
}

// Transpose+convert W1 [e][k=1024][n=512] fp32 -> [e][n][k] fp16 hi/lo
__global__ void k_convW1(const float* __restrict__ src) {
    __shared__ float tile[32][33];
    int e = blockIdx.z;
    int kb = blockIdx.x * 32, nb = blockIdx.y * 32;
    const float* s = src + ((size_t)e * FDIM1 + kb) * FDIM2 + nb;
    int tx = threadIdx.x, ty = threadIdx.y;
#pragma unroll
    for (int i = 0; i < 32; i += 8) tile[ty + i][tx] = s[(size_t)(ty + i) * FDIM2 + tx];
    __syncthreads();
    size_t ob = ((size_t)e * FDIM2 + nb) * FDIM1 + kb;
#pragma unroll
    for (int i = 0; i < 32; i += 8) {
        float v = tile[tx][ty + i];
        __half h = __float2half_rn(v);
        __half l = __float2half_rn(v - __half2float(h));
        g_W1t_hi[ob + (size_t)(ty + i) * FDIM1 + tx] = h;
        g_W1t_lo[ob + (size_t)(ty + i) * FDIM1 + tx] = l;
    }
}

// Transpose+convert W2 [e][k=512][n=64] fp32 -> [e][n][k] fp16 hi/lo
__global__ void k_convW2(const float* __restrict__ src) {
    __shared__ float tile[32][33];
    int e = blockIdx.z;
    int kb = blockIdx.x * 32, nb = blockIdx.y * 32;
    const float* s = src + ((size_t)e * FDIM2 + kb) * NCLS + nb;
    int tx = threadIdx.x, ty = threadIdx.y;
#pragma unroll
    for (int i = 0; i < 32; i += 8) tile[ty + i][tx] = s[(size_t)(ty + i) * NCLS + tx];
    __syncthreads();
    size_t ob = ((size_t)e * NCLS + nb) * FDIM2 + kb;
#pragma unroll
    for (int i = 0; i < 32; i += 8) {
        float v = tile[tx][ty + i];
        __half h = __float2half_rn(v);
        __half l = __float2half_rn(v - __half2float(h));
        g_W2t_hi[ob + (size_t)(ty + i) * FDIM2 + tx] = h;
        g_W2t_lo[ob + (size_t)(ty + i) * FDIM2 + tx] = l;
    }
}

// ---------------- layer 1: fp16 mma.sync GEMM (2-pass: A*Bh + A*Bl) ---------
// CTA: 128 rows x 128 cols, K=1024 in 32 chunks of 32. 8 warps = 2(M) x 4(N).
// 2-stage double buffer; B via cp.async, A via fp32 LDG + pack + STS.
// Dynamic smem layout (bytes):
//   [0,512)        int rows[128]
//   [512,1024)     float bias[128]
//   [1024,21504)   sA[2][128*APITCH] halfs (10240 B/stage)
//   [21504,41984)  sBh[2][...]
//   [41984,62464)  sBl[2][...]
#define L1_ROWS 0
#define L1_BIAS 512
#define L1_A 1024
#define L1_BH 21504
#define L1_BL 41984
#define L1_STG 10240
#define L1_SMEM 62464

__global__ __launch_bounds__(256, 2) void k_gemm1(
    const float* __restrict__ x, const float* __restrict__ b1)
{
    const int e = blockIdx.z;
    const int cnt = g_cnt[e];
    const int mbase = blockIdx.x * 128;
    if (mbase >= cnt) return;
    const int nbase = blockIdx.y * 128;

    extern __shared__ __align__(16) char sm1[];
    int* rows = (int*)(sm1 + L1_ROWS);
    float* bias = (float*)(sm1 + L1_BIAS);
    const uint32_t sb = smem_u32(sm1);
    const uint32_t aA = sb + L1_A, aBh = sb + L1_BH, aBl = sb + L1_BL;

    const int t = threadIdx.x;
    if (t < 128) {
        int p = mbase + t;
        rows[t] = (p < cnt) ? g_idx[e * BATCH + p] : -1;
        bias[t] = b1[e * FDIM2 + nbase + t];
    }
    __syncthreads();

    // ---- load mappings
    const int lr = t >> 1;             // row 0..127 (A and B share mapping)
    const int lo16 = (t & 1) * 16;     // 16-half offset within 32-half chunk row
    const int xr = rows[lr];
    const float* xp = (xr >= 0) ? x + (size_t)xr * FDIM1 + lo16 : nullptr;
    const __half* wph = g_W1t_hi + (size_t)(e * FDIM2 + nbase + lr) * FDIM1 + lo16;
    const __half* wpl = g_W1t_lo + (size_t)(e * FDIM2 + nbase + lr) * FDIM1 + lo16;
    // smem dst for this thread's B segs: row*80B + (t&1)*32B
    const uint32_t bOff = lr * (APITCH * 2) + (t & 1) * 32;

    float4 xa[4];

#define L1_LOADA(kc)                                                       \
    do {                                                                   \
        if (xp) {                                                          \
            const float4* s4 = (const float4*)(xp + (kc));                 \
            xa[0] = s4[0]; xa[1] = s4[1]; xa[2] = s4[2]; xa[3] = s4[3];    \
        } else {                                                           \
            xa[0] = xa[1] = xa[2] = xa[3] = make_float4(0.f, 0.f, 0.f, 0.f); \
        }                                                                  \
    } while (0)

#define L1_ISSUEB(kc, stg)                                                 \
    do {                                                                   \
        uint32_t so = (stg) * L1_STG + bOff;                               \
        cpasync16(aBh + so,      wph + (kc));                              \
        cpasync16(aBh + so + 16, wph + (kc) + 8);                          \
        cpasync16(aBl + so,      wpl + (kc));                              \
        cpasync16(aBl + so + 16, wpl + (kc) + 8);                          \
        CP_COMMIT();                                                       \
    } while (0)

    const int l = t & 31, wid = t >> 5;
    const int wm = (wid >> 2) * 64, wn = (wid & 3) * 32;
    const int lrow = l & 15;
    const int lk = (l >> 4) * 8;

    float acc[4][4][4];
#pragma unroll
    for (int i = 0; i < 4; i++)
#pragma unroll
        for (int j = 0; j < 4; j++)
#pragma unroll
            for (int q = 0; q < 4; q++) acc[i][j][q] = 0.f;

    // prologue: B chunk 0 in flight, A chunk 0 in regs
    L1_ISSUEB(0, 0);
    L1_LOADA(0);

    for (int c = 0; c < 32; c++) {
        const int stg = c & 1;
        __syncthreads();  // compute(c-1) fully done: safe to overwrite stage (c&1)

        // store A regs (chunk c) into sA[stg]
        {
            uint32_t p0 = packh2(xa[0].x, xa[0].y), p1 = packh2(xa[0].z, xa[0].w);
            uint32_t p2 = packh2(xa[1].x, xa[1].y), p3 = packh2(xa[1].z, xa[1].w);
            uint32_t p4 = packh2(xa[2].x, xa[2].y), p5 = packh2(xa[2].z, xa[2].w);
            uint32_t p6 = packh2(xa[3].x, xa[3].y), p7 = packh2(xa[3].z, xa[3].w);
            uint32_t d = aA + stg * L1_STG + lr * (APITCH * 2) + lo16 * 2;
            *(uint4*)(uintptr_t)(__cvta_shared_to_generic(d)) = make_uint4(p0, p1, p2, p3);
            *(uint4*)(uintptr_t)(__cvta_shared_to_generic(d + 16)) = make_uint4(p4, p5, p6, p7);
        }

        if (c + 1 < 32) {
            L1_ISSUEB((c + 1) * 32, stg ^ 1);  // next B into other stage
            L1_LOADA((c + 1) * 32);            // next A into regs
            CP_WAIT(1);                        // B(c) landed; B(c+1) in flight
        } else {
            CP_WAIT(0);
        }
        __syncthreads();

        // ---- compute chunk c from stage stg
        const uint32_t sOff = stg * L1_STG;
#pragma unroll
        for (int ks = 0; ks < 32; ks += 16) {
            uint32_t ah[4][4], bh[4][2], bl[4][2];
#pragma unroll
            for (int mt = 0; mt < 4; mt++) {
                uint32_t off = sOff + ((wm + mt * 16 + lrow) * APITCH + ks + lk) * 2;
                ldsm4(ah[mt][0], ah[mt][1], ah[mt][2], ah[mt][3], aA + off);
            }
#pragma unroll
            for (int bg = 0; bg < 2; bg++) {
                uint32_t off = sOff + ((wn + bg * 16 + lrow) * APITCH + ks + lk) * 2;
                uint32_t r0, r1, r2, r3;
                ldsm4(r0, r1, r2, r3, aBh + off);
                bh[2 * bg][0] = r0; bh[2 * bg + 1][0] = r1;
                bh[2 * bg][1] = r2; bh[2 * bg + 1][1] = r3;
                ldsm4(r0, r1, r2, r3, aBl + off);
                bl[2 * bg][0] = r0; bl[2 * bg + 1][0] = r1;
                bl[2 * bg][1] = r2; bl[2 * bg + 1][1] = r3;
            }
#pragma unroll
            for (int mt = 0; mt < 4; mt++)
#pragma unroll
                for (int nt = 0; nt < 4; nt++) {
                    mma_fp16(acc[mt][nt], ah[mt], bh[nt][0], bh[nt][1]);
                    mma_fp16(acc[mt][nt], ah[mt], bl[nt][0], bl[nt][1]);
                }
        }
    }

    // epilogue: + bias, relu, fp16, scatter to g_H
#pragma unroll
    for (int mt = 0; mt < 4; mt++) {
        int r0i = wm + mt * 16 + (l >> 2);
        int ra = rows[r0i], rb = rows[r0i + 8];
#pragma unroll
        for (int nt = 0; nt < 4; nt++) {
            int cl = wn + nt * 8 + (l & 3) * 2;
            float b0 = bias[cl], b1v = bias[cl + 1];
            if (ra >= 0) {
                uint32_t h = packh2(fmaxf(acc[mt][nt][0] + b0, 0.f),
                                    fmaxf(acc[mt][nt][1] + b1v, 0.f));
                *(uint32_t*)(&g_H[(size_t)ra * FDIM2 + nbase + cl]) = h;
            }
            if (rb >= 0) {
                uint32_t h = packh2(fmaxf(acc[mt][nt][2] + b0, 0.f),
                                    fmaxf(acc[mt][nt][3] + b1v, 0.f));
                *(uint32_t*)(&g_H[(size_t)rb * FDIM2 + nbase + cl]) = h;
            }
        }
    }
#undef L1_LOADA
#undef L1_ISSUEB
}

// ---------------- layer 2: fp16 mma.sync GEMM + softmax ---------------------
// CTA: 128 rows x 64 cols, K=512 in 16 chunks of 32. 8 warps = 4(M) x 2(N).
#define SM2_A 0
#define SM2_BH 10240
#define SM2_BL 15360
#define SM2_SZ 34816  /* union with logits: 128 x 68 floats */

__global__ __launch_bounds__(256) void k_gemm2(
    const float* __restrict__ b2, float* __restrict__ out)
{
    const int e = blockIdx.y;
    const int cnt = g_cnt[e];
    const int mbase = blockIdx.x * 128;
    if (mbase >= cnt) return;

    __shared__ int rows[128];
    __shared__ float b2s[64];
    __shared__ __align__(16) char sm[SM2_SZ];

    const int t = threadIdx.x;
    if (t < 128) {
        int p = mbase + t;
        rows[t] = (p < cnt) ? g_idx[e * BATCH + p] : -1;
    }
    if (t < 64) b2s[t] = b2[e * NCLS + t];
    __syncthreads();

    __half* sA = (__half*)(sm + SM2_A);
    __half* sBh = (__half*)(sm + SM2_BH);
    __half* sBl = (__half*)(sm + SM2_BL);

    const int lr = t >> 1;
    const int lo16 = (t & 1) * 16;
    const int hr = rows[lr];
    const __half* hp = (hr >= 0) ? g_H + (size_t)hr * FDIM2 + lo16 : nullptr;
    const int bt = t & 127;
    const int br = bt >> 1, blo16 = (bt & 1) * 16;
    const __half* wp =
        ((t < 128) ? g_W2t_hi : g_W2t_lo) + (size_t)(e * NCLS + br) * FDIM2 + blo16;
    __half* sB = (t < 128) ? sBh : sBl;

    uint4 ha[2], wb[2];

#define L2_LOAD(kc)                                                       \
    do {                                                                  \
        if (hp) {                                                         \
            ha[0] = *(const uint4*)(hp + (kc));                           \
            ha[1] = *(const uint4*)(hp + (kc) + 8);                       \
        } else {                                                          \
            ha[0] = ha[1] = make_uint4(0, 0, 0, 0);                       \
        }                                                                 \
        wb[0] = *(const uint4*)(wp + (kc));                               \
        wb[1] = *(const uint4*)(wp + (kc) + 8);                           \
    } while (0)

    const int l = t & 31, wid = t >> 5;
    const int wm = (wid >> 1) * 32, wn = (wid & 1) * 32;
    const uint32_t aA = smem_u32(sA);
    const uint32_t aBh = smem_u32(sBh), aBl = smem_u32(sBl);
    const int lrow = l & 15;
    const int lk = (l >> 4) * 8;

    float acc[2][4][4];
#pragma unroll
    for (int i = 0; i < 2; i++)
#pragma unroll
        for (int j = 0; j < 4; j++)
#pragma unroll
            for (int q = 0; q < 4; q++) acc[i][j][q] = 0.f;

    L2_LOAD(0);

    for (int c = 0; c < 16; c++) {
        __syncthreads();
        *(uint4*)(&sA[lr * APITCH + lo16])      = ha[0];
        *(uint4*)(&sA[lr * APITCH + lo16 + 8])  = ha[1];
        *(uint4*)(&sB[br * APITCH + blo16])     = wb[0];
        *(uint4*)(&sB[br * APITCH + blo16 + 8]) = wb[1];
        __syncthreads();
        if (c < 15) L2_LOAD((c + 1) * 32);

#pragma unroll
        for (int ks = 0; ks < 32; ks += 16) {
            uint32_t ah[2][4], bh[4][2], bl[4][2];
#pragma unroll
            for (int mt = 0; mt < 2; mt++) {
                uint32_t off = ((wm + mt * 16 + lrow) * APITCH + ks + lk) * 2;
                ldsm4(ah[mt][0], ah[mt][1], ah[mt][2], ah[mt][3], aA + off);
            }
#pragma unroll
            for (int bg = 0; bg < 2; bg++) {
                uint32_t off = ((wn + bg * 16 + lrow) * APITCH + ks + lk) * 2;
                uint32_t r0, r1, r2, r3;
                ldsm4(r0, r1, r2, r3, aBh + off);
                bh[2 * bg][0] = r0; bh[2 * bg + 1][0] = r1;
                bh[2 * bg][1] = r2; bh[2 * bg + 1][1] = r3;
                ldsm4(r0, r1, r2, r3, aBl + off);
                bl[2 * bg][0] = r0; bl[2 * bg + 1][0] = r1;
                bl[2 * bg][1] = r2; bl[2 * bg + 1][1] = r3;
            }
#pragma unroll
            for (int mt = 0; mt < 2; mt++)
#pragma unroll
                for (int nt = 0; nt < 4; nt++) {
                    mma_fp16(acc[mt][nt], ah[mt], bh[nt][0], bh[nt][1]);
                    mma_fp16(acc[mt][nt], ah[mt], bl[nt][0], bl[nt][1]);
                }
        }
    }

    // logits -> smem (union over A/B buffers), then per-thread softmax
    __syncthreads();
    float* lg = (float*)sm;  // [128][68]
#pragma unroll
    for (int mt = 0; mt < 2; mt++) {
        int r0i = wm + mt * 16 + (l >> 2);
#pragma unroll
        for (int nt = 0; nt < 4; nt++) {
            int cl = wn + nt * 8 + (l & 3) * 2;
            lg[r0i * 68 + cl]           = acc[mt][nt][0];
            lg[r0i * 68 + cl + 1]       = acc[mt][nt][1];
            lg[(r0i + 8) * 68 + cl]     = acc[mt][nt][2];
            lg[(r0i + 8) * 68 + cl + 1] = acc[mt][nt][3];
        }
    }
    __syncthreads();

    if (t < 128) {
        int r = rows[t];
        if (r >= 0) {
            float v[64];
            float mx = -3.4e38f;
#pragma unroll
            for (int j = 0; j < 64; j++) {
                v[j] = lg[t * 68 + j] + b2s[j];
                mx = fmaxf(mx, v[j]);
            }
            float s = 0.f;
#pragma unroll
            for (int j = 0; j < 64; j++) {
                v[j] = __expf(v[j] - mx);
                s += v[j];
            }
            float inv = 1.0f / s;
            float4* op = (float4*)(out + (size_t)r * NCLS);
#pragma unroll
            for (int q = 0; q < 16; q++)
                op[q] = make_float4(v[4 * q] * inv, v[4 * q + 1] * inv,
                                    v[4 * q + 2] * inv, v[4 * q + 3] * inv);
        }
    }
#undef L2_LOAD
}

// ---------------------------------------------------------------------------
extern "C" void kernel_launch(void* const* d_in, const int* in_sizes, int n_in,
                              void* d_out, int out_size)
{
    const int*   domain = (const int*)  d_in[0];
    const float* x      = (const float*)d_in[1];
    const float* W1     = (const float*)d_in[2];
    const float* b1     = (const float*)d_in[3];
    const float* W2     = (const float*)d_in[4];
    const float* b2     = (const float*)d_in[5];
    float* out = (float*)d_out;

    static int smem_set = 0;
    if (!smem_set) {
        cudaFuncSetAttribute(k_gemm1, cudaFuncAttributeMaxDynamicSharedMemorySize, L1_SMEM);
        smem_set = 1;
    }

    k_reset<<<1, 32>>>();
    k_bucket<<<BATCH / 256, 256>>>(domain);
    k_convW1<<<dim3(FDIM1 / 32, FDIM2 / 32, N_EXPERTS), dim3(32, 8)>>>(W1);
    k_convW2<<<dim3(FDIM2 / 32, NCLS / 32, N_EXPERTS), dim3(32, 8)>>>(W2);
    k_gemm1<<<dim3(BATCH / 128, FDIM2 / 128, N_EXPERTS), 256, L1_SMEM>>>(x, b1);
    k_gemm2<<<dim3(BATCH / 128, N_EXPERTS), 256>>>(b2, out);
}

// round 6
// speedup vs baseline: 3.3387x; 1.2969x over previous
#include <cuda_runtime.h>
#include <cuda_fp16.h>
#include <cstdint>

#define N_EXPERTS 8
#define FDIM1 1024
#define FDIM2 512
#define NCLS 64
#define BATCH 16384
#define APITCH 40   // smem row pitch in fp16 elems (32 + 8 pad: conflict-free ldmatrix)

// ---------------- scratch (static device arrays; allocation-free) ----------
__device__ __align__(16) __half g_W1t[N_EXPERTS * FDIM2 * FDIM1];
__device__ __align__(16) __half g_W2t[N_EXPERTS * NCLS * FDIM2];
__device__ __align__(16) __half g_H[(size_t)BATCH * FDIM2];
__device__ int g_idx[N_EXPERTS * BATCH];
__device__ int g_cnt[N_EXPERTS];

// ---------------- helpers ---------------------------------------------------
__device__ __forceinline__ uint32_t smem_u32(const void* p) {
    uint32_t a;
    asm("{ .reg .u64 t; cvta.to.shared.u64 t, %1; cvt.u32.u64 %0, t; }"
        : "=r"(a) : "l"(p));
    return a;
}

__device__ __forceinline__ void ldsm4(uint32_t& r0, uint32_t& r1, uint32_t& r2,
                                      uint32_t& r3, uint32_t addr) {
    asm volatile("ldmatrix.sync.aligned.m8n8.x4.shared.b16 {%0,%1,%2,%3}, [%4];"
                 : "=r"(r0), "=r"(r1), "=r"(r2), "=r"(r3) : "r"(addr));
}

__device__ __forceinline__ void mma_fp16(float* c, const uint32_t* a,
                                         uint32_t b0, uint32_t b1) {
    asm volatile(
        "mma.sync.aligned.m16n8k16.row.col.f32.f16.f16.f32 "
        "{%0,%1,%2,%3}, {%4,%5,%6,%7}, {%8,%9}, {%0,%1,%2,%3};"
        : "+f"(c[0]), "+f"(c[1]), "+f"(c[2]), "+f"(c[3])
        : "r"(a[0]), "r"(a[1]), "r"(a[2]), "r"(a[3]), "r"(b0), "r"(b1));
}

__device__ __forceinline__ void cpasync16(uint32_t dst, const void* src) {
    asm volatile("cp.async.ca.shared.global [%0], [%1], 16;"
                 :: "r"(dst), "l"(src) : "memory");
}
#define CP_COMMIT() asm volatile("cp.async.commit_group;" ::: "memory")
#define CP_WAIT(n) asm volatile("cp.async.wait_group %0;" ::"n"(n) : "memory")

__device__ __forceinline__ uint32_t packh2(float v0, float v1) {
    __half2 h = __floats2half2_rn(v0, v1);
    return *(uint32_t*)&h;
}

// ---------------- small kernels ---------------------------------------------
__global__ void k_reset() {
    if (threadIdx.x < N_EXPERTS) g_cnt[threadIdx.x] = 0;
}

__global__ void k_bucket(const int* __restrict__ domain) {
    int i = blockIdx.x * blockDim.x + threadIdx.x;
    if (i < BATCH) {
        int e = domain[i];
        int p = atomicAdd(&g_cnt[e], 1);
        g_idx[e * BATCH + p] = i;
    }
}

// Transpose+convert W1 [e][k=1024][n=512] fp32 -> [e][n][k] fp16
__global__ void k_convW1(const float* __restrict__ src) {
    __shared__ float tile[32][33];
    int e = blockIdx.z;
    int kb = blockIdx.x * 32, nb = blockIdx.y * 32;
    const float* s = src + ((size_t)e * FDIM1 + kb) * FDIM2 + nb;
    int tx = threadIdx.x, ty = threadIdx.y;
#pragma unroll
    for (int i = 0; i < 32; i += 8) tile[ty + i][tx] = s[(size_t)(ty + i) * FDIM2 + tx];
    __syncthreads();
    size_t ob = ((size_t)e * FDIM2 + nb) * FDIM1 + kb;
#pragma unroll
    for (int i = 0; i < 32; i += 8)
        g_W1t[ob + (size_t)(ty + i) * FDIM1 + tx] = __float2half_rn(tile[tx][ty + i]);
}

// Transpose+convert W2 [e][k=512][n=64] fp32 -> [e][n][k] fp16
__global__ void k_convW2(const float* __restrict__ src) {
    __shared__ float tile[32][33];
    int e = blockIdx.z;
    int kb = blockIdx.x * 32, nb = blockIdx.y * 32;
    const float* s = src + ((size_t)e * FDIM2 + kb) * NCLS + nb;
    int tx = threadIdx.x, ty = threadIdx.y;
#pragma unroll
    for (int i = 0; i < 32; i += 8) tile[ty + i][tx] = s[(size_t)(ty + i) * NCLS + tx];
    __syncthreads();
    size_t ob = ((size_t)e * NCLS + nb) * FDIM2 + kb;
#pragma unroll
    for (int i = 0; i < 32; i += 8)
        g_W2t[ob + (size_t)(ty + i) * FDIM2 + tx] = __float2half_rn(tile[tx][ty + i]);
}

// ---------------- layer 1: fp16 mma.sync GEMM (single pass) -----------------
// CTA: 128 rows x 128 cols, K=1024 in 32 chunks of 32. 8 warps = 2(M) x 4(N).
// 2-stage double buffer; B via cp.async, A via fp32 LDG + pack + STS.
// Dynamic smem layout (bytes):
//   [0,512)        int rows[128]
//   [512,1024)     float bias[128]
//   [1024,21504)   sA[2][128*APITCH] halfs (10240 B/stage)
//   [21504,41984)  sB[2][...]
#define L1_ROWS 0
#define L1_BIAS 512
#define L1_A 1024
#define L1_B 21504
#define L1_STG 10240
#define L1_SMEM 41984

__global__ __launch_bounds__(256, 2) void k_gemm1(
    const float* __restrict__ x, const float* __restrict__ b1)
{
    const int e = blockIdx.z;
    const int cnt = g_cnt[e];
    const int mbase = blockIdx.x * 128;
    if (mbase >= cnt) return;
    const int nbase = blockIdx.y * 128;

    extern __shared__ __align__(16) char sm1[];
    int* rows = (int*)(sm1 + L1_ROWS);
    float* bias = (float*)(sm1 + L1_BIAS);
    const uint32_t sb = smem_u32(sm1);
    const uint32_t aA = sb + L1_A, aB = sb + L1_B;

    const int t = threadIdx.x;
    if (t < 128) {
        int p = mbase + t;
        rows[t] = (p < cnt) ? g_idx[e * BATCH + p] : -1;
        bias[t] = b1[e * FDIM2 + nbase + t];
    }
    __syncthreads();

    // ---- load mappings
    const int lr = t >> 1;             // row 0..127 (A and B share mapping)
    const int lo16 = (t & 1) * 16;     // 16-half offset within 32-half chunk row
    const int xr = rows[lr];
    const float* xp = (xr >= 0) ? x + (size_t)xr * FDIM1 + lo16 : nullptr;
    const __half* wp = g_W1t + (size_t)(e * FDIM2 + nbase + lr) * FDIM1 + lo16;
    const uint32_t bOff = lr * (APITCH * 2) + (t & 1) * 32;

    float4 xa[4];

#define L1_LOADA(kc)                                                       \
    do {                                                                   \
        if (xp) {                                                          \
            const float4* s4 = (const float4*)(xp + (kc));                 \
            xa[0] = s4[0]; xa[1] = s4[1]; xa[2] = s4[2]; xa[3] = s4[3];    \
        } else {                                                           \
            xa[0] = xa[1] = xa[2] = xa[3] = make_float4(0.f, 0.f, 0.f, 0.f); \
        }                                                                  \
    } while (0)

#define L1_ISSUEB(kc, stg)                                                 \
    do {                                                                   \
        uint32_t so = (stg) * L1_STG + bOff;                               \
        cpasync16(aB + so,      wp + (kc));                                \
        cpasync16(aB + so + 16, wp + (kc) + 8);                            \
        CP_COMMIT();                                                       \
    } while (0)

    const int l = t & 31, wid = t >> 5;
    const int wm = (wid >> 2) * 64, wn = (wid & 3) * 32;
    const int lrow = l & 15;
    const int lk = (l >> 4) * 8;

    float acc[4][4][4];
#pragma unroll
    for (int i = 0; i < 4; i++)
#pragma unroll
        for (int j = 0; j < 4; j++)
#pragma unroll
            for (int q = 0; q < 4; q++) acc[i][j][q] = 0.f;

    // prologue: B chunk 0 in flight, A chunk 0 in regs
    L1_ISSUEB(0, 0);
    L1_LOADA(0);

    for (int c = 0; c < 32; c++) {
        const int stg = c & 1;
        __syncthreads();  // compute(c-1) fully done: safe to overwrite stage (c&1)

        // store A regs (chunk c) into sA[stg]
        {
            uint32_t p0 = packh2(xa[0].x, xa[0].y), p1 = packh2(xa[0].z, xa[0].w);
            uint32_t p2 = packh2(xa[1].x, xa[1].y), p3 = packh2(xa[1].z, xa[1].w);
            uint32_t p4 = packh2(xa[2].x, xa[2].y), p5 = packh2(xa[2].z, xa[2].w);
            uint32_t p6 = packh2(xa[3].x, xa[3].y), p7 = packh2(xa[3].z, xa[3].w);
            uint32_t d = aA + stg * L1_STG + lr * (APITCH * 2) + lo16 * 2;
            *(uint4*)(uintptr_t)(__cvta_shared_to_generic(d)) = make_uint4(p0, p1, p2, p3);
            *(uint4*)(uintptr_t)(__cvta_shared_to_generic(d + 16)) = make_uint4(p4, p5, p6, p7);
        }

        if (c + 1 < 32) {
            L1_ISSUEB((c + 1) * 32, stg ^ 1);  // next B into other stage
            L1_LOADA((c + 1) * 32);            // next A into regs
            CP_WAIT(1);                        // B(c) landed; B(c+1) in flight
        } else {
            CP_WAIT(0);
        }
        __syncthreads();

        // ---- compute chunk c from stage stg
        const uint32_t sOff = stg * L1_STG;
#pragma unroll
        for (int ks = 0; ks < 32; ks += 16) {
            uint32_t ah[4][4], bh[4][2];
#pragma unroll
            for (int mt = 0; mt < 4; mt++) {
                uint32_t off = sOff + ((wm + mt * 16 + lrow) * APITCH + ks + lk) * 2;
                ldsm4(ah[mt][0], ah[mt][1], ah[mt][2], ah[mt][3], aA + off);
            }
#pragma unroll
            for (int bg = 0; bg < 2; bg++) {
                uint32_t off = sOff + ((wn + bg * 16 + lrow) * APITCH + ks + lk) * 2;
                uint32_t r0, r1, r2, r3;
                ldsm4(r0, r1, r2, r3, aB + off);
                bh[2 * bg][0] = r0; bh[2 * bg + 1][0] = r1;
                bh[2 * bg][1] = r2; bh[2 * bg + 1][1] = r3;
            }
#pragma unroll
            for (int mt = 0; mt < 4; mt++)
#pragma unroll
                for (int nt = 0; nt < 4; nt++)
                    mma_fp16(acc[mt][nt], ah[mt], bh[nt][0], bh[nt][1]);
        }
    }

    // epilogue: + bias, relu, fp16, scatter to g_H
#pragma unroll
    for (int mt = 0; mt < 4; mt++) {
        int r0i = wm + mt * 16 + (l >> 2);
        int ra = rows[r0i], rb = rows[r0i + 8];
#pragma unroll
        for (int nt = 0; nt < 4; nt++) {
            int cl = wn + nt * 8 + (l & 3) * 2;
            float b0 = bias[cl], b1v = bias[cl + 1];
            if (ra >= 0) {
                uint32_t h = packh2(fmaxf(acc[mt][nt][0] + b0, 0.f),
                                    fmaxf(acc[mt][nt][1] + b1v, 0.f));
                *(uint32_t*)(&g_H[(size_t)ra * FDIM2 + nbase + cl]) = h;
            }
            if (rb >= 0) {
                uint32_t h = packh2(fmaxf(acc[mt][nt][2] + b0, 0.f),
                                    fmaxf(acc[mt][nt][3] + b1v, 0.f));
                *(uint32_t*)(&g_H[(size_t)rb * FDIM2 + nbase + cl]) = h;
            }
        }
    }
#undef L1_LOADA
#undef L1_ISSUEB
}

// ---------------- layer 2: fp16 mma.sync GEMM + softmax ---------------------
// CTA: 128 rows x 64 cols, K=512 in 16 chunks of 32. 8 warps = 4(M) x 2(N).
#define SM2_A 0
#define SM2_B 10240
#define SM2_SZ 34816  /* union with logits: 128 x 68 floats */

__global__ __launch_bounds__(256) void k_gemm2(
    const float* __restrict__ b2, float* __restrict__ out)
{
    const int e = blockIdx.y;
    const int cnt = g_cnt[e];
    const int mbase = blockIdx.x * 128;
    if (mbase >= cnt) return;

    __shared__ int rows[128];
    __shared__ float b2s[64];
    __shared__ __align__(16) char sm[SM2_SZ];

    const int t = threadIdx.x;
    if (t < 128) {
        int p = mbase + t;
        rows[t] = (p < cnt) ? g_idx[e * BATCH + p] : -1;
    }
    if (t < 64) b2s[t] = b2[e * NCLS + t];
    __syncthreads();

    __half* sA = (__half*)(sm + SM2_A);
    __half* sB = (__half*)(sm + SM2_B);

    const int lr = t >> 1;
    const int lo16 = (t & 1) * 16;
    const int hr = rows[lr];
    const __half* hp = (hr >= 0) ? g_H + (size_t)hr * FDIM2 + lo16 : nullptr;
    // B: 64 rows x 32 halfs per chunk; 256 threads load one uint4 (8 halfs) each
    const int br = t >> 2, blo8 = (t & 3) * 8;
    const __half* wp = g_W2t + (size_t)(e * NCLS + br) * FDIM2 + blo8;

    uint4 ha[2], wb;

#define L2_LOAD(kc)                                                       \
    do {                                                                  \
        if (hp) {                                                         \
            ha[0] = *(const uint4*)(hp + (kc));                           \
            ha[1] = *(const uint4*)(hp + (kc) + 8);                       \
        } else {                                                          \
            ha[0] = ha[1] = make_uint4(0, 0, 0, 0);                       \
        }                                                                 \
        wb = *(const uint4*)(wp + (kc));                                  \
    } while (0)

    const int l = t & 31, wid = t >> 5;
    const int wm = (wid >> 1) * 32, wn = (wid & 1) * 32;
    const uint32_t aA = smem_u32(sA);
    const uint32_t aB = smem_u32(sB);
    const int lrow = l & 15;
    const int lk = (l >> 4) * 8;

    float acc[2][4][4];
#pragma unroll
    for (int i = 0; i < 2; i++)
#pragma unroll
        for (int j = 0; j < 4; j++)
#pragma unroll
            for (int q = 0; q < 4; q++) acc[i][j][q] = 0.f;

    L2_LOAD(0);

    for (int c = 0; c < 16; c++) {
        __syncthreads();
        *(uint4*)(&sA[lr * APITCH + lo16])      = ha[0];
        *(uint4*)(&sA[lr * APITCH + lo16 + 8])  = ha[1];
        *(uint4*)(&sB[br * APITCH + blo8])      = wb;
        __syncthreads();
        if (c < 15) L2_LOAD((c + 1) * 32);

#pragma unroll
        for (int ks = 0; ks < 32; ks += 16) {
            uint32_t ah[2][4], bh[4][2];
#pragma unroll
            for (int mt = 0; mt < 2; mt++) {
                uint32_t off = ((wm + mt * 16 + lrow) * APITCH + ks + lk) * 2;
                ldsm4(ah[mt][0], ah[mt][1], ah[mt][2], ah[mt][3], aA + off);
            }
#pragma unroll
            for (int bg = 0; bg < 2; bg++) {
                uint32_t off = ((wn + bg * 16 + lrow) * APITCH + ks + lk) * 2;
                uint32_t r0, r1, r2, r3;
                ldsm4(r0, r1, r2, r3, aB + off);
                bh[2 * bg][0] = r0; bh[2 * bg + 1][0] = r1;
                bh[2 * bg][1] = r2; bh[2 * bg + 1][1] = r3;
            }
#pragma unroll
            for (int mt = 0; mt < 2; mt++)
#pragma unroll
                for (int nt = 0; nt < 4; nt++)
                    mma_fp16(acc[mt][nt], ah[mt], bh[nt][0], bh[nt][1]);
        }
    }

    // logits -> smem (union over A/B buffers), then per-thread softmax
    __syncthreads();
    float* lg = (float*)sm;  // [128][68]
#pragma unroll
    for (int mt = 0; mt < 2; mt++) {
        int r0i = wm + mt * 16 + (l >> 2);
#pragma unroll
        for (int nt = 0; nt < 4; nt++) {
            int cl = wn + nt * 8 + (l & 3) * 2;
            lg[r0i * 68 + cl]           = acc[mt][nt][0];
            lg[r0i * 68 + cl + 1]       = acc[mt][nt][1];
            lg[(r0i + 8) * 68 + cl]     = acc[mt][nt][2];
            lg[(r0i + 8) * 68 + cl + 1] = acc[mt][nt][3];
        }
    }
    __syncthreads();

    if (t < 128) {
        int r = rows[t];
        if (r >= 0) {
            float v[64];
            float mx = -3.4e38f;
#pragma unroll
            for (int j = 0; j < 64; j++) {
                v[j] = lg[t * 68 + j] + b2s[j];
                mx = fmaxf(mx, v[j]);
            }
            float s = 0.f;
#pragma unroll
            for (int j = 0; j < 64; j++) {
                v[j] = __expf(v[j] - mx);
                s += v[j];
            }
            float inv = 1.0f / s;
            float4* op = (float4*)(out + (size_t)r * NCLS);
#pragma unroll
            for (int q = 0; q < 16; q++)
                op[q] = make_float4(v[4 * q] * inv, v[4 * q + 1] * inv,
                                    v[4 * q + 2] * inv, v[4 * q + 3] * inv);
        }
    }
#undef L2_LOAD
}

// ---------------------------------------------------------------------------
extern "C" void kernel_launch(void* const* d_in, const int* in_sizes, int n_in,
                              void* d_out, int out_size)
{
    const int*   domain = (const int*)  d_in[0];
    const float* x      = (const float*)d_in[1];
    const float* W1     = (const float*)d_in[2];
    const float* b1     = (const float*)d_in[3];
    const float* W2     = (const float*)d_in[4];
    const float* b2     = (const float*)d_in[5];
    float* out = (float*)d_out;

    static int smem_set = 0;
    if (!smem_set) {
        cudaFuncSetAttribute(k_gemm1, cudaFuncAttributeMaxDynamicSharedMemorySize, L1_SMEM);
        smem_set = 1;
    }

    k_reset<<<1, 32>>>();
    k_bucket<<<BATCH / 256, 256>>>(domain);
    k_convW1<<<dim3(FDIM1 / 32, FDIM2 / 32, N_EXPERTS), dim3(32, 8)>>>(W1);
    k_convW2<<<dim3(FDIM2 / 32, NCLS / 32, N_EXPERTS), dim3(32, 8)>>>(W2);
    k_gemm1<<<dim3(BATCH / 128, FDIM2 / 128, N_EXPERTS), 256, L1_SMEM>>>(x, b1);
    k_gemm2<<<dim3(BATCH / 128, N_EXPERTS), 256>>>(b2, out);
}